// round 6
// baseline (speedup 1.0000x reference)
#include <cuda_runtime.h>
#include <math.h>
#include <stdint.h>

namespace {
constexpr int B_ = 64;
constexpr int T_ = 512;
constexpr int I_ = 512;
constexpr int H_ = 1024;
constexpr int G_ = 3 * H_;     // 3072
constexpr int NBLK = 128;      // persistent blocks
constexpr int NTHR = 256;
constexpr int BH = B_ * H_;

constexpr int HRP = 132;       // staging row pad (u32): bank stride 4, frag LDS conflict-free
constexpr int RP = 26;         // reduce row pad
constexpr int RING = 4;
constexpr int HR_F = RING * 64 * HRP;   // 33792 u32
constexpr int RED_F = 8 * 64 * RP;      // 13312 fl
constexpr int REC_SMEM = (HR_F + RED_F) * 4;  // 188416 bytes
}

// Scratch (device globals -- no runtime allocation)
__device__ float g_xg[(size_t)B_ * T_ * G_];
__device__ float g_hseq[(size_t)B_ * T_ * H_];
__device__ __align__(16) uint32_t g_htf[2 * BH];   // h in tf32 bits, ping-pong
__device__ unsigned g_barcnt[2 * T_];

// ---- tf32 helpers ----
__device__ __forceinline__ uint32_t f2tf(float x) {
    uint32_t r;
    asm("cvt.rna.tf32.f32 %0, %1;" : "=r"(r) : "f"(x));
    return r;
}
__device__ __forceinline__ float4 cvt4(float4 v) {
    return make_float4(__uint_as_float(f2tf(v.x)), __uint_as_float(f2tf(v.y)),
                       __uint_as_float(f2tf(v.z)), __uint_as_float(f2tf(v.w)));
}
// m16n8k8 tf32 mma, D += A*B
__device__ __forceinline__ void mma8(float* d, const uint32_t* a, const uint32_t* b) {
    asm volatile(
        "mma.sync.aligned.m16n8k8.row.col.f32.tf32.tf32.f32 "
        "{%0,%1,%2,%3}, {%4,%5,%6,%7}, {%8,%9}, {%0,%1,%2,%3};"
        : "+f"(d[0]), "+f"(d[1]), "+f"(d[2]), "+f"(d[3])
        : "r"(a[0]), "r"(a[1]), "r"(a[2]), "r"(a[3]), "r"(b[0]), "r"(b[1]));
}
__device__ __forceinline__ uint32_t smem_u32(const void* p) {
    uint32_t a;
    asm("{ .reg .u64 t; cvta.to.shared.u64 t, %1; cvt.u32.u64 %0, t; }" : "=r"(a) : "l"(p));
    return a;
}

// ---- grid barrier ----
__device__ __forceinline__ void grid_bar(unsigned* cnt) {
    __threadfence();
    __syncthreads();
    if (threadIdx.x == 0) {
        asm volatile("red.release.gpu.global.add.u32 [%0], 1;" :: "l"(cnt) : "memory");
        unsigned v;
        do {
            asm volatile("ld.acquire.gpu.global.u32 %0, [%1];" : "=r"(v) : "l"(cnt) : "memory");
        } while (v < (unsigned)NBLK);
    }
    __syncthreads();
}

__global__ void reset_barriers() { g_barcnt[threadIdx.x] = 0; }

// ============================================================================
// xg = A[M][K] @ W[G][K]^T + b_ih (+ b_hh folded for r/z gates)
// tf32 mma.sync, tile 128x128x16, double buffered. (verified, unchanged)
// ============================================================================
__global__ __launch_bounds__(256) void xg_gemm(
    const float* __restrict__ A_ext, int use_hseq,
    const float* __restrict__ W,
    const float* __restrict__ bih, const float* __restrict__ bhh,
    int K)
{
    __shared__ __align__(16) float sA[2][128][20];
    __shared__ __align__(16) float sB[2][128][20];
    const float* __restrict__ A = use_hseq ? (const float*)g_hseq : A_ext;

    const int tid = threadIdx.x;
    const int lane = tid & 31, wid = tid >> 5;
    const int g = lane >> 2, tig = lane & 3;
    const int wm = wid & 3, wn = wid >> 2;
    const int m0 = blockIdx.y * 128, n0 = blockIdx.x * 128;
    const int mrow = tid >> 1;
    const int kh = (tid & 1) * 8;

    float acc[2][8][4];
#pragma unroll
    for (int mi = 0; mi < 2; mi++)
#pragma unroll
        for (int ni = 0; ni < 8; ni++)
#pragma unroll
            for (int q = 0; q < 4; q++) acc[mi][ni][q] = 0.f;

    const int nch = K >> 4;
    {
        const float* ap = A + (size_t)(m0 + mrow) * K + kh;
        const float* bp = W + (size_t)(n0 + mrow) * K + kh;
        float4 a0 = *(const float4*)ap, a1 = *(const float4*)(ap + 4);
        float4 b0 = *(const float4*)bp, b1 = *(const float4*)(bp + 4);
        *(float4*)&sA[0][mrow][kh] = cvt4(a0);
        *(float4*)&sA[0][mrow][kh + 4] = cvt4(a1);
        *(float4*)&sB[0][mrow][kh] = cvt4(b0);
        *(float4*)&sB[0][mrow][kh + 4] = cvt4(b1);
    }
    __syncthreads();

    for (int ch = 0; ch < nch; ch++) {
        float4 la0, la1, lb0, lb1;
        if (ch + 1 < nch) {
            const float* ap = A + (size_t)(m0 + mrow) * K + (ch + 1) * 16 + kh;
            const float* bp = W + (size_t)(n0 + mrow) * K + (ch + 1) * 16 + kh;
            la0 = *(const float4*)ap; la1 = *(const float4*)(ap + 4);
            lb0 = *(const float4*)bp; lb1 = *(const float4*)(bp + 4);
        }
        const int buf = ch & 1;
#pragma unroll
        for (int s = 0; s < 2; s++) {
            const int k0 = s * 8;
            uint32_t af[2][4];
#pragma unroll
            for (int mi = 0; mi < 2; mi++) {
                int mb = wm * 32 + mi * 16;
                af[mi][0] = __float_as_uint(sA[buf][mb + g][k0 + tig]);
                af[mi][1] = __float_as_uint(sA[buf][mb + 8 + g][k0 + tig]);
                af[mi][2] = __float_as_uint(sA[buf][mb + g][k0 + tig + 4]);
                af[mi][3] = __float_as_uint(sA[buf][mb + 8 + g][k0 + tig + 4]);
            }
#pragma unroll
            for (int ni = 0; ni < 8; ni++) {
                int nb = wn * 64 + ni * 8;
                uint32_t bf[2];
                bf[0] = __float_as_uint(sB[buf][nb + g][k0 + tig]);
                bf[1] = __float_as_uint(sB[buf][nb + g][k0 + tig + 4]);
                mma8(acc[0][ni], af[0], bf);
                mma8(acc[1][ni], af[1], bf);
            }
        }
        if (ch + 1 < nch) {
            const int nb2 = buf ^ 1;
            *(float4*)&sA[nb2][mrow][kh] = cvt4(la0);
            *(float4*)&sA[nb2][mrow][kh + 4] = cvt4(la1);
            *(float4*)&sB[nb2][mrow][kh] = cvt4(lb0);
            *(float4*)&sB[nb2][mrow][kh + 4] = cvt4(lb1);
        }
        __syncthreads();
    }

#pragma unroll
    for (int mi = 0; mi < 2; mi++) {
        int m = m0 + wm * 32 + mi * 16 + g;
#pragma unroll
        for (int ni = 0; ni < 8; ni++) {
            int n = n0 + wn * 64 + ni * 8 + 2 * tig;
            float b0 = bih[n], b1 = bih[n + 1];
            if (n < 2 * H_) { b0 += bhh[n]; b1 += bhh[n + 1]; }
            *(float2*)(g_xg + (size_t)m * G_ + n) =
                make_float2(acc[mi][ni][0] + b0, acc[mi][ni][1] + b1);
            *(float2*)(g_xg + (size_t)(m + 8) * G_ + n) =
                make_float2(acc[mi][ni][2] + b0, acc[mi][ni][3] + b1);
        }
    }
}

// ============================================================================
// Persistent recurrence: block owns 8 hidden cols, W_hh in registers.
// h_{t-1} (tf32) staged in 128-k chunks via cp.async, ring of 4, one
// __syncthreads per chunk. xg gate values prefetched at step top.
// ============================================================================
__global__ void __launch_bounds__(NTHR, 1) gru_rec(
    const float* __restrict__ Whh, const float* __restrict__ bhh,
    int layer, float* __restrict__ final_out)
{
    extern __shared__ uint32_t smu[];
    uint32_t* hring = smu;                    // [RING][64][HRP] tf32 bits
    float* red = (float*)(smu + HR_F);        // [8][64][RP]

    const int tid = threadIdx.x;
    const int lane = tid & 31, wid = tid >> 5;
    const int g = lane >> 2, tig = lane & 3;
    const int j0 = blockIdx.x * 8;
    const uint32_t hring_b = smem_u32(hring);

    // W_hh fragments -> registers. breg[cc][s][ni]: chunk cc(128k), slot pair s.
    uint32_t breg[8][2][3][2];
#pragma unroll
    for (int cc = 0; cc < 8; cc++)
#pragma unroll
        for (int s = 0; s < 2; s++)
#pragma unroll
            for (int ni = 0; ni < 3; ni++) {
                const float* wp = Whh + (size_t)(ni * H_ + j0 + g) * H_
                                  + cc * 128 + (s * 8 + wid) * 8 + tig;
                breg[cc][s][ni][0] = f2tf(wp[0]);
                breg[cc][s][ni][1] = f2tf(wp[4]);
            }
    const float bhn0 = bhh[2 * H_ + j0 + ((tid * 2) & 7)];
    const float bhn1 = bhh[2 * H_ + j0 + ((tid * 2 + 1) & 7)];
    float hreg[2] = {0.f, 0.f};

    unsigned* barBase = g_barcnt + layer * T_;
    const int srow = tid >> 2;        // 0..63 staging row
    const int sc0 = (tid & 3) * 4;    // staging col base (u32)

    for (int t = 0; t < T_; t++) {
        // ---- prefetch gate inputs for this step (hide LDG latency) ----
        float xpre[2][3];
#pragma unroll
        for (int e = 0; e < 2; e++) {
            int ii = tid * 2 + e;
            int b = ii >> 3, jj = ii & 7;
            const float* xp = g_xg + ((size_t)b * T_ + t) * G_ + j0 + jj;
            xpre[e][0] = xp[0];
            xpre[e][1] = xp[H_];
            xpre[e][2] = xp[2 * H_];
        }

        float gr[2] = {0.f, 0.f}, gz[2] = {0.f, 0.f}, gn[2] = {0.f, 0.f};

        if (t > 0) {
            const uint32_t* hre = g_htf + (size_t)((t - 1) & 1) * BH;

            float acc[4][3][4];
#pragma unroll
            for (int mt = 0; mt < 4; mt++)
#pragma unroll
                for (int ni = 0; ni < 3; ni++)
#pragma unroll
                    for (int q = 0; q < 4; q++) acc[mt][ni][q] = 0.f;

            // prime chunks 0..2 (each 64 rows x 128 k = 32KB)
#pragma unroll
            for (int p = 0; p < 3; p++) {
                uint32_t d = hring_b + (uint32_t)((p * 64 + srow) * HRP + sc0) * 4u;
                const uint32_t* s = hre + (size_t)srow * H_ + p * 128 + sc0;
#pragma unroll
                for (int r = 0; r < 8; r++) {
                    asm volatile("cp.async.cg.shared.global [%0], [%1], 16;"
                                 :: "r"(d + r * 64u), "l"(s + r * 16) : "memory");
                }
                asm volatile("cp.async.commit_group;" ::: "memory");
            }

#pragma unroll
            for (int cc = 0; cc < 8; cc++) {
                if (cc <= 5)      asm volatile("cp.async.wait_group 2;" ::: "memory");
                else if (cc == 6) asm volatile("cp.async.wait_group 1;" ::: "memory");
                else              asm volatile("cp.async.wait_group 0;" ::: "memory");
                __syncthreads();

                // issue chunk cc+3 into ring buffer (cc+3)&3 (retired at iter cc-1)
                if (cc + 3 < 8) {
                    const int p = cc + 3;
                    uint32_t d = hring_b + (uint32_t)((((p) & 3) * 64 + srow) * HRP + sc0) * 4u;
                    const uint32_t* s = hre + (size_t)srow * H_ + p * 128 + sc0;
#pragma unroll
                    for (int r = 0; r < 8; r++) {
                        asm volatile("cp.async.cg.shared.global [%0], [%1], 16;"
                                     :: "r"(d + r * 64u), "l"(s + r * 16) : "memory");
                    }
                    asm volatile("cp.async.commit_group;" ::: "memory");
                }

                const uint32_t* ab = hring + (cc & 3) * 64 * HRP;
#pragma unroll
                for (int s = 0; s < 2; s++) {
                    const int kl = (s * 8 + wid) * 8;
#pragma unroll
                    for (int mt = 0; mt < 4; mt++) {
                        const uint32_t* r0 = ab + (mt * 16 + g) * HRP + kl + tig;
                        const uint32_t* r1 = ab + (mt * 16 + 8 + g) * HRP + kl + tig;
                        uint32_t af[4] = {r0[0], r1[0], r0[4], r1[4]};
#pragma unroll
                        for (int ni = 0; ni < 3; ni++)
                            mma8(acc[mt][ni], af, breg[cc][s][ni]);
                    }
                }
            }

            // ---- 8-way k reduce via smem ----
#pragma unroll
            for (int mt = 0; mt < 4; mt++)
#pragma unroll
                for (int ni = 0; ni < 3; ni++) {
                    float* p0 = red + (size_t)(wid * 64 + mt * 16 + g) * RP + ni * 8 + 2 * tig;
                    *(float2*)p0 = make_float2(acc[mt][ni][0], acc[mt][ni][1]);
                    float* p1 = red + (size_t)(wid * 64 + mt * 16 + 8 + g) * RP + ni * 8 + 2 * tig;
                    *(float2*)p1 = make_float2(acc[mt][ni][2], acc[mt][ni][3]);
                }
            __syncthreads();

#pragma unroll
            for (int e = 0; e < 2; e++) {
                int ii = tid * 2 + e;
                int b = ii >> 3, jj = ii & 7;
#pragma unroll
                for (int p = 0; p < 8; p++) {
                    const float* rp = red + (size_t)(p * 64 + b) * RP;
                    gr[e] += rp[jj];
                    gz[e] += rp[8 + jj];
                    gn[e] += rp[16 + jj];
                }
            }
        }

        // ---- gates ----
#pragma unroll
        for (int e = 0; e < 2; e++) {
            int ii = tid * 2 + e;
            int b = ii >> 3, jj = ii & 7;
            int col = j0 + jj;
            float r = 1.f / (1.f + expf(-(xpre[e][0] + gr[e])));
            float z = 1.f / (1.f + expf(-(xpre[e][1] + gz[e])));
            float bn = e ? bhn1 : bhn0;
            float n = tanhf(xpre[e][2] + r * (gn[e] + bn));
            float hnew = (1.f - z) * n + z * hreg[e];
            hreg[e] = hnew;

            g_htf[(size_t)(t & 1) * BH + (size_t)b * H_ + col] = f2tf(hnew);
            if (layer == 0) {
                g_hseq[((size_t)b * T_ + t) * H_ + col] = hnew;
            } else if (t == T_ - 1) {
                final_out[(size_t)b * H_ + col] = hnew;
            }
        }

        if (t < T_ - 1) grid_bar(barBase + t);
    }
}

// ============================================================================
extern "C" void kernel_launch(void* const* d_in, const int* in_sizes, int n_in,
                              void* d_out, int out_size)
{
    const float* x    = (const float*)d_in[0];
    const float* wih0 = (const float*)d_in[1];
    const float* whh0 = (const float*)d_in[2];
    const float* bih0 = (const float*)d_in[3];
    const float* bhh0 = (const float*)d_in[4];
    const float* wih1 = (const float*)d_in[5];
    const float* whh1 = (const float*)d_in[6];
    const float* bih1 = (const float*)d_in[7];
    const float* bhh1 = (const float*)d_in[8];
    float* out = (float*)d_out;

    cudaFuncSetAttribute(gru_rec, cudaFuncAttributeMaxDynamicSharedMemorySize, REC_SMEM);

    dim3 gg(G_ / 128, (B_ * T_) / 128);   // 24 x 256

    reset_barriers<<<1, 2 * T_>>>();

    xg_gemm<<<gg, 256>>>(x, 0, wih0, bih0, bhh0, I_);
    gru_rec<<<NBLK, NTHR, REC_SMEM>>>(whh0, bhh0, 0, out);

    xg_gemm<<<gg, 256>>>(nullptr, 1, wih1, bih1, bhh1, H_);
    gru_rec<<<NBLK, NTHR, REC_SMEM>>>(whh1, bhh1, 1, out);
}

// round 7
// speedup vs baseline: 1.4720x; 1.4720x over previous
#include <cuda_runtime.h>
#include <cuda_fp16.h>
#include <math.h>
#include <stdint.h>

namespace {
constexpr int B_ = 64;
constexpr int T_ = 512;
constexpr int I_ = 512;
constexpr int H_ = 1024;
constexpr int G_ = 3 * H_;     // 3072
constexpr int NBLK = 128;      // persistent blocks
constexpr int NTHR = 256;
constexpr int BH = B_ * H_;

constexpr int HP = 68;         // rec staging row pad (u32) -> bank stride 4
constexpr int RP = 26;         // reduce row pad
constexpr int RING = 4;
constexpr int HR_F = RING * 64 * HP;    // 17408 u32
constexpr int RED_F = 8 * 64 * RP;      // 13312 fl
constexpr int REC_SMEM = (HR_F + RED_F) * 4;  // 122880 bytes
}

// Scratch (device globals -- no runtime allocation)
__device__ float g_xg[(size_t)B_ * T_ * G_];            // xg (fp32)
__device__ __align__(16) uint32_t g_ah[(size_t)B_ * T_ * H_ / 2]; // layer input, fp16 pairs
__device__ __align__(16) uint32_t g_wh[(size_t)G_ * H_ / 2];      // w_ih fp16 pairs
__device__ __align__(16) uint32_t g_hh[BH];             // h fp16 pairs, ping-pong (2*BH halves)
__device__ unsigned g_barcnt[2 * T_];

// ---- helpers ----
__device__ __forceinline__ uint32_t pack2(float x, float y) {
    __half2 h = __floats2half2_rn(x, y);
    return *(uint32_t*)&h;
}
// m16n8k16 fp16 mma, fp32 accum
__device__ __forceinline__ void mma16(float* d, const uint32_t* a, const uint32_t* b) {
    asm volatile(
        "mma.sync.aligned.m16n8k16.row.col.f32.f16.f16.f32 "
        "{%0,%1,%2,%3}, {%4,%5,%6,%7}, {%8,%9}, {%0,%1,%2,%3};"
        : "+f"(d[0]), "+f"(d[1]), "+f"(d[2]), "+f"(d[3])
        : "r"(a[0]), "r"(a[1]), "r"(a[2]), "r"(a[3]), "r"(b[0]), "r"(b[1]));
}
__device__ __forceinline__ uint32_t smem_u32(const void* p) {
    uint32_t a;
    asm("{ .reg .u64 t; cvta.to.shared.u64 t, %1; cvt.u32.u64 %0, t; }" : "=r"(a) : "l"(p));
    return a;
}

// ---- grid barrier ----
__device__ __forceinline__ void grid_bar(unsigned* cnt) {
    __threadfence();
    __syncthreads();
    if (threadIdx.x == 0) {
        asm volatile("red.release.gpu.global.add.u32 [%0], 1;" :: "l"(cnt) : "memory");
        unsigned v;
        do {
            asm volatile("ld.acquire.gpu.global.u32 %0, [%1];" : "=r"(v) : "l"(cnt) : "memory");
        } while (v < (unsigned)NBLK);
    }
    __syncthreads();
}

__global__ void reset_barriers() { g_barcnt[threadIdx.x] = 0; }

// ---- fp32 -> fp16 conversion (vectorized) ----
__global__ __launch_bounds__(256) void cvt16(const float* __restrict__ in,
                                             uint32_t* __restrict__ out, int n4) {
    int i = blockIdx.x * 256 + threadIdx.x;
    if (i < n4) {
        float4 v = ((const float4*)in)[i];
        ((uint2*)out)[i] = make_uint2(pack2(v.x, v.y), pack2(v.z, v.w));
    }
}

// ============================================================================
// xg = A[M][K] @ W[G][K]^T + b_ih (+ b_hh folded for r/z gates)
// fp16 mma.sync m16n8k16, tile 128x128x32, double buffered. 8 warps = 4m x 2n.
// A, W read as packed fp16 (u32 pairs).
// ============================================================================
__global__ __launch_bounds__(256) void xg_gemm(
    const uint32_t* __restrict__ A,   // [M][K/2]
    const uint32_t* __restrict__ W,   // [G][K/2]
    const float* __restrict__ bih, const float* __restrict__ bhh,
    int K)
{
    __shared__ __align__(16) uint32_t sA[2][128][20];   // 40 halves/row
    __shared__ __align__(16) uint32_t sB[2][128][20];

    const int tid = threadIdx.x;
    const int lane = tid & 31, wid = tid >> 5;
    const int g = lane >> 2, tig = lane & 3;
    const int wm = wid & 3, wn = wid >> 2;
    const int m0 = blockIdx.y * 128, n0 = blockIdx.x * 128;
    const int K2 = K >> 1;                     // row stride in u32
    const int mrow = tid >> 1;
    const int kq = (tid & 1) * 8;              // u32 offset within 16-u32 chunk row

    float acc[2][8][4];
#pragma unroll
    for (int mi = 0; mi < 2; mi++)
#pragma unroll
        for (int ni = 0; ni < 8; ni++)
#pragma unroll
            for (int q = 0; q < 4; q++) acc[mi][ni][q] = 0.f;

    const int nch = K >> 5;                    // 32-k chunks
    {
        const uint32_t* ap = A + (size_t)(m0 + mrow) * K2 + kq;
        const uint32_t* bp = W + (size_t)(n0 + mrow) * K2 + kq;
        *(uint4*)&sA[0][mrow][kq] = *(const uint4*)ap;
        *(uint4*)&sA[0][mrow][kq + 4] = *(const uint4*)(ap + 4);
        *(uint4*)&sB[0][mrow][kq] = *(const uint4*)bp;
        *(uint4*)&sB[0][mrow][kq + 4] = *(const uint4*)(bp + 4);
    }
    __syncthreads();

    for (int ch = 0; ch < nch; ch++) {
        uint4 la0, la1, lb0, lb1;
        if (ch + 1 < nch) {
            const uint32_t* ap = A + (size_t)(m0 + mrow) * K2 + (ch + 1) * 16 + kq;
            const uint32_t* bp = W + (size_t)(n0 + mrow) * K2 + (ch + 1) * 16 + kq;
            la0 = *(const uint4*)ap; la1 = *(const uint4*)(ap + 4);
            lb0 = *(const uint4*)bp; lb1 = *(const uint4*)(bp + 4);
        }
        const int buf = ch & 1;
#pragma unroll
        for (int s = 0; s < 2; s++) {          // 2 k16 slots per chunk
            const int c0 = s * 8;
            uint32_t af[2][4];
#pragma unroll
            for (int mi = 0; mi < 2; mi++) {
                int mb = wm * 32 + mi * 16;
                af[mi][0] = sA[buf][mb + g][c0 + tig];
                af[mi][1] = sA[buf][mb + 8 + g][c0 + tig];
                af[mi][2] = sA[buf][mb + g][c0 + tig + 4];
                af[mi][3] = sA[buf][mb + 8 + g][c0 + tig + 4];
            }
#pragma unroll
            for (int ni = 0; ni < 8; ni++) {
                int nb = wn * 64 + ni * 8;
                uint32_t bf[2];
                bf[0] = sB[buf][nb + g][c0 + tig];
                bf[1] = sB[buf][nb + g][c0 + tig + 4];
                mma16(acc[0][ni], af[0], bf);
                mma16(acc[1][ni], af[1], bf);
            }
        }
        if (ch + 1 < nch) {
            const int nb2 = buf ^ 1;
            *(uint4*)&sA[nb2][mrow][kq] = la0;
            *(uint4*)&sA[nb2][mrow][kq + 4] = la1;
            *(uint4*)&sB[nb2][mrow][kq] = lb0;
            *(uint4*)&sB[nb2][mrow][kq + 4] = lb1;
        }
        __syncthreads();
    }

#pragma unroll
    for (int mi = 0; mi < 2; mi++) {
        int m = m0 + wm * 32 + mi * 16 + g;
#pragma unroll
        for (int ni = 0; ni < 8; ni++) {
            int n = n0 + wn * 64 + ni * 8 + 2 * tig;
            float b0 = bih[n], b1 = bih[n + 1];
            if (n < 2 * H_) { b0 += bhh[n]; b1 += bhh[n + 1]; }
            *(float2*)(g_xg + (size_t)m * G_ + n) =
                make_float2(acc[mi][ni][0] + b0, acc[mi][ni][1] + b1);
            *(float2*)(g_xg + (size_t)(m + 8) * G_ + n) =
                make_float2(acc[mi][ni][2] + b0, acc[mi][ni][3] + b1);
        }
    }
}

// ============================================================================
// Persistent recurrence: block owns 8 hidden cols, W_hh in 48 fp16x2 regs.
// h_{t-1} (fp16) staged in 128-k chunks (16KB) via cp.async, ring of 4.
// 8 warps = k16 slots. fp32 accum, 8-way smem reduce, gates, grid barrier.
// ============================================================================
__global__ void __launch_bounds__(NTHR, 1) gru_rec(
    const float* __restrict__ Whh, const float* __restrict__ bhh,
    int layer, float* __restrict__ final_out)
{
    extern __shared__ uint32_t smu[];
    uint32_t* hring = smu;                    // [RING][64][HP]
    float* red = (float*)(smu + HR_F);        // [8][64][RP]

    const int tid = threadIdx.x;
    const int lane = tid & 31, wid = tid >> 5;   // wid = k16 slot within chunk
    const int g = lane >> 2, tig = lane & 3;
    const int j0 = blockIdx.x * 8;
    const uint32_t hring_b = smem_u32(hring);

    // W_hh -> fp16 register fragments. breg[cc][ni]: chunk cc (128k), gate-tile ni.
    uint32_t breg[8][3][2];
#pragma unroll
    for (int cc = 0; cc < 8; cc++)
#pragma unroll
        for (int ni = 0; ni < 3; ni++) {
            const float* wp = Whh + (size_t)(ni * H_ + j0 + g) * H_
                              + cc * 128 + wid * 16 + 2 * tig;
            breg[cc][ni][0] = pack2(wp[0], wp[1]);
            breg[cc][ni][1] = pack2(wp[8], wp[9]);
        }
    const float bhn0 = bhh[2 * H_ + j0 + ((tid * 2) & 7)];
    const float bhn1 = bhh[2 * H_ + j0 + ((tid * 2 + 1) & 7)];
    float hreg[2] = {0.f, 0.f};

    unsigned* barBase = g_barcnt + layer * T_;
    const int srow = tid >> 2;        // 0..63 staging row
    const int sc0 = (tid & 3) * 4;    // staging col base (u32)

    for (int t = 0; t < T_; t++) {
        // prefetch gate inputs (hide LDG latency behind the mma pipeline)
        const int b0i = (tid * 2) >> 3, jj0 = (tid * 2) & 7;
        const float* xp = g_xg + ((size_t)b0i * T_ + t) * G_ + j0 + jj0;
        float2 xr2 = *(const float2*)xp;
        float2 xz2 = *(const float2*)(xp + H_);
        float2 xn2 = *(const float2*)(xp + 2 * H_);

        float gr[2] = {0.f, 0.f}, gz[2] = {0.f, 0.f}, gn[2] = {0.f, 0.f};

        if (t > 0) {
            const uint32_t* hre = g_hh + (size_t)((t - 1) & 1) * (BH / 2);

            float acc[4][3][4];
#pragma unroll
            for (int mt = 0; mt < 4; mt++)
#pragma unroll
                for (int ni = 0; ni < 3; ni++)
#pragma unroll
                    for (int q = 0; q < 4; q++) acc[mt][ni][q] = 0.f;

            // prime chunks 0..2 (16KB each)
#pragma unroll
            for (int p = 0; p < 3; p++) {
                uint32_t d = hring_b + (uint32_t)((p * 64 + srow) * HP + sc0) * 4u;
                const uint32_t* s = hre + (size_t)srow * (H_ / 2) + p * 64 + sc0;
#pragma unroll
                for (int r = 0; r < 4; r++) {
                    asm volatile("cp.async.cg.shared.global [%0], [%1], 16;"
                                 :: "r"(d + r * 64u), "l"(s + r * 16) : "memory");
                }
                asm volatile("cp.async.commit_group;" ::: "memory");
            }

#pragma unroll
            for (int cc = 0; cc < 8; cc++) {
                if (cc <= 5)      asm volatile("cp.async.wait_group 2;" ::: "memory");
                else if (cc == 6) asm volatile("cp.async.wait_group 1;" ::: "memory");
                else              asm volatile("cp.async.wait_group 0;" ::: "memory");
                __syncthreads();

                if (cc + 3 < 8) {
                    const int p = cc + 3;
                    uint32_t d = hring_b + (uint32_t)(((p & 3) * 64 + srow) * HP + sc0) * 4u;
                    const uint32_t* s = hre + (size_t)srow * (H_ / 2) + p * 64 + sc0;
#pragma unroll
                    for (int r = 0; r < 4; r++) {
                        asm volatile("cp.async.cg.shared.global [%0], [%1], 16;"
                                     :: "r"(d + r * 64u), "l"(s + r * 16) : "memory");
                    }
                    asm volatile("cp.async.commit_group;" ::: "memory");
                }

                const uint32_t* ab = hring + (cc & 3) * 64 * HP;
                const int kl = wid * 8;       // u32 offset of this warp's k16 slot
#pragma unroll
                for (int mt = 0; mt < 4; mt++) {
                    const uint32_t* r0 = ab + (mt * 16 + g) * HP + kl + tig;
                    const uint32_t* r1 = ab + (mt * 16 + 8 + g) * HP + kl + tig;
                    uint32_t af[4] = {r0[0], r1[0], r0[4], r1[4]};
#pragma unroll
                    for (int ni = 0; ni < 3; ni++)
                        mma16(acc[mt][ni], af, breg[cc][ni]);
                }
            }

            // 8-way k reduce via smem
#pragma unroll
            for (int mt = 0; mt < 4; mt++)
#pragma unroll
                for (int ni = 0; ni < 3; ni++) {
                    float* p0 = red + (size_t)(wid * 64 + mt * 16 + g) * RP + ni * 8 + 2 * tig;
                    *(float2*)p0 = make_float2(acc[mt][ni][0], acc[mt][ni][1]);
                    float* p1 = red + (size_t)(wid * 64 + mt * 16 + 8 + g) * RP + ni * 8 + 2 * tig;
                    *(float2*)p1 = make_float2(acc[mt][ni][2], acc[mt][ni][3]);
                }
            __syncthreads();

#pragma unroll
            for (int e = 0; e < 2; e++) {
                int jj = jj0 + e;
#pragma unroll
                for (int p = 0; p < 8; p++) {
                    const float* rp = red + (size_t)(p * 64 + b0i) * RP;
                    gr[e] += rp[jj];
                    gz[e] += rp[8 + jj];
                    gn[e] += rp[16 + jj];
                }
            }
        }

        // ---- gates: 2 adjacent outputs per thread ----
        float hn0, hn1;
        {
            float r = 1.f / (1.f + expf(-(xr2.x + gr[0])));
            float z = 1.f / (1.f + expf(-(xz2.x + gz[0])));
            float n = tanhf(xn2.x + r * (gn[0] + bhn0));
            hn0 = (1.f - z) * n + z * hreg[0];
            hreg[0] = hn0;
        }
        {
            float r = 1.f / (1.f + expf(-(xr2.y + gr[1])));
            float z = 1.f / (1.f + expf(-(xz2.y + gz[1])));
            float n = tanhf(xn2.y + r * (gn[1] + bhn1));
            hn1 = (1.f - z) * n + z * hreg[1];
            hreg[1] = hn1;
        }
        const int col = j0 + jj0;
        g_hh[(size_t)(t & 1) * (BH / 2) + (((size_t)b0i * H_ + col) >> 1)] = pack2(hn0, hn1);
        if (layer == 0) {
            g_ah[(((size_t)b0i * T_ + t) * H_ + col) >> 1] = pack2(hn0, hn1);
        } else if (t == T_ - 1) {
            *(float2*)(final_out + (size_t)b0i * H_ + col) = make_float2(hn0, hn1);
        }

        if (t < T_ - 1) grid_bar(barBase + t);
    }
}

// ============================================================================
extern "C" void kernel_launch(void* const* d_in, const int* in_sizes, int n_in,
                              void* d_out, int out_size)
{
    const float* x    = (const float*)d_in[0];
    const float* wih0 = (const float*)d_in[1];
    const float* whh0 = (const float*)d_in[2];
    const float* bih0 = (const float*)d_in[3];
    const float* bhh0 = (const float*)d_in[4];
    const float* wih1 = (const float*)d_in[5];
    const float* whh1 = (const float*)d_in[6];
    const float* bih1 = (const float*)d_in[7];
    const float* bhh1 = (const float*)d_in[8];
    float* out = (float*)d_out;

    cudaFuncSetAttribute(gru_rec, cudaFuncAttributeMaxDynamicSharedMemorySize, REC_SMEM);

    uint32_t* ah;  cudaGetSymbolAddress((void**)&ah, g_ah);
    uint32_t* wh;  cudaGetSymbolAddress((void**)&wh, g_wh);

    dim3 gg(G_ / 128, (B_ * T_) / 128);   // 24 x 256

    reset_barriers<<<1, 2 * T_>>>();

    // layer 0: convert x and w_ih0 to fp16
    {
        int n4x = B_ * T_ * I_ / 4;
        cvt16<<<(n4x + 255) / 256, 256>>>(x, ah, n4x);
        int n4w = G_ * I_ / 4;
        cvt16<<<(n4w + 255) / 256, 256>>>(wih0, wh, n4w);
    }
    xg_gemm<<<gg, 256>>>(ah, wh, bih0, bhh0, I_);
    gru_rec<<<NBLK, NTHR, REC_SMEM>>>(whh0, bhh0, 0, out);   // writes g_ah (fp16 hseq)

    // layer 1: convert w_ih1; A is already fp16 in g_ah
    {
        int n4w = G_ * H_ / 4;
        cvt16<<<(n4w + 255) / 256, 256>>>(wih1, wh, n4w);
    }
    xg_gemm<<<gg, 256>>>(ah, wh, bih1, bhh1, H_);
    gru_rec<<<NBLK, NTHR, REC_SMEM>>>(whh1, bhh1, 1, out);
}

// round 8
// speedup vs baseline: 1.9723x; 1.3399x over previous
#include <cuda_runtime.h>
#include <cuda_fp16.h>
#include <math.h>
#include <stdint.h>

namespace {
constexpr int B_ = 64;
constexpr int T_ = 512;
constexpr int I_ = 512;
constexpr int H_ = 1024;
constexpr int G_ = 3 * H_;     // 3072
constexpr int NBLK = 128;      // persistent blocks
constexpr int NTHR = 256;
constexpr int BH = B_ * H_;

constexpr int WP = 516;        // W smem row pad (u32) -> bank stride 4
constexpr int HSP = 516;       // h slice row pad (u32)
constexpr int RPD = 50;        // reduce row pad (floats, even)
constexpr int WS_U = 48 * WP;          // 24768 u32
constexpr int HS_U = 32 * HSP;         // 16512 u32
constexpr int RED_U = 4 * 32 * RPD;    // 6400
constexpr int REC_SMEM = (WS_U + HS_U + RED_U) * 4;   // 190720 bytes
}

// Scratch (device globals -- no runtime allocation)
__device__ float g_xg[(size_t)B_ * T_ * G_];            // xg (fp32)
__device__ __align__(16) uint32_t g_ah[(size_t)B_ * T_ * H_ / 2]; // layer input, fp16 pairs
__device__ __align__(16) uint32_t g_wh[(size_t)G_ * H_ / 2];      // w_ih fp16 pairs
__device__ __align__(16) uint32_t g_hh[BH];             // h fp16 pairs, ping-pong
__device__ unsigned g_barcnt[2 * T_];

// ---- helpers ----
__device__ __forceinline__ uint32_t pack2(float x, float y) {
    __half2 h = __floats2half2_rn(x, y);
    return *(uint32_t*)&h;
}
// m16n8k16 fp16 mma, fp32 accum
__device__ __forceinline__ void mma16(float* d, const uint32_t* a, const uint32_t* b) {
    asm volatile(
        "mma.sync.aligned.m16n8k16.row.col.f32.f16.f16.f32 "
        "{%0,%1,%2,%3}, {%4,%5,%6,%7}, {%8,%9}, {%0,%1,%2,%3};"
        : "+f"(d[0]), "+f"(d[1]), "+f"(d[2]), "+f"(d[3])
        : "r"(a[0]), "r"(a[1]), "r"(a[2]), "r"(a[3]), "r"(b[0]), "r"(b[1]));
}
__device__ __forceinline__ uint32_t smem_u32(const void* p) {
    uint32_t a;
    asm("{ .reg .u64 t; cvta.to.shared.u64 t, %1; cvt.u32.u64 %0, t; }" : "=r"(a) : "l"(p));
    return a;
}

// ---- grid barrier ----
__device__ __forceinline__ void grid_bar(unsigned* cnt) {
    __threadfence();
    __syncthreads();
    if (threadIdx.x == 0) {
        asm volatile("red.release.gpu.global.add.u32 [%0], 1;" :: "l"(cnt) : "memory");
        unsigned v;
        do {
            asm volatile("ld.acquire.gpu.global.u32 %0, [%1];" : "=r"(v) : "l"(cnt) : "memory");
        } while (v < (unsigned)NBLK);
    }
    __syncthreads();
}

__global__ void reset_barriers() { g_barcnt[threadIdx.x] = 0; }

// ---- fp32 -> fp16 conversion (vectorized) ----
__global__ __launch_bounds__(256) void cvt16(const float* __restrict__ in,
                                             uint32_t* __restrict__ out, int n4) {
    int i = blockIdx.x * 256 + threadIdx.x;
    if (i < n4) {
        float4 v = ((const float4*)in)[i];
        ((uint2*)out)[i] = make_uint2(pack2(v.x, v.y), pack2(v.z, v.w));
    }
}

// ============================================================================
// xg = A[M][K] @ W[G][K]^T + b_ih (+ b_hh folded for r/z gates)
// fp16 mma.sync m16n8k16, tile 128x128x32, double buffered. (verified R7)
// ============================================================================
__global__ __launch_bounds__(256) void xg_gemm(
    const uint32_t* __restrict__ A,   // [M][K/2]
    const uint32_t* __restrict__ W,   // [G][K/2]
    const float* __restrict__ bih, const float* __restrict__ bhh,
    int K)
{
    __shared__ __align__(16) uint32_t sA[2][128][20];
    __shared__ __align__(16) uint32_t sB[2][128][20];

    const int tid = threadIdx.x;
    const int lane = tid & 31, wid = tid >> 5;
    const int g = lane >> 2, tig = lane & 3;
    const int wm = wid & 3, wn = wid >> 2;
    const int m0 = blockIdx.y * 128, n0 = blockIdx.x * 128;
    const int K2 = K >> 1;
    const int mrow = tid >> 1;
    const int kq = (tid & 1) * 8;

    float acc[2][8][4];
#pragma unroll
    for (int mi = 0; mi < 2; mi++)
#pragma unroll
        for (int ni = 0; ni < 8; ni++)
#pragma unroll
            for (int q = 0; q < 4; q++) acc[mi][ni][q] = 0.f;

    const int nch = K >> 5;
    {
        const uint32_t* ap = A + (size_t)(m0 + mrow) * K2 + kq;
        const uint32_t* bp = W + (size_t)(n0 + mrow) * K2 + kq;
        *(uint4*)&sA[0][mrow][kq] = *(const uint4*)ap;
        *(uint4*)&sA[0][mrow][kq + 4] = *(const uint4*)(ap + 4);
        *(uint4*)&sB[0][mrow][kq] = *(const uint4*)bp;
        *(uint4*)&sB[0][mrow][kq + 4] = *(const uint4*)(bp + 4);
    }
    __syncthreads();

    for (int ch = 0; ch < nch; ch++) {
        uint4 la0, la1, lb0, lb1;
        if (ch + 1 < nch) {
            const uint32_t* ap = A + (size_t)(m0 + mrow) * K2 + (ch + 1) * 16 + kq;
            const uint32_t* bp = W + (size_t)(n0 + mrow) * K2 + (ch + 1) * 16 + kq;
            la0 = *(const uint4*)ap; la1 = *(const uint4*)(ap + 4);
            lb0 = *(const uint4*)bp; lb1 = *(const uint4*)(bp + 4);
        }
        const int buf = ch & 1;
#pragma unroll
        for (int s = 0; s < 2; s++) {
            const int c0 = s * 8;
            uint32_t af[2][4];
#pragma unroll
            for (int mi = 0; mi < 2; mi++) {
                int mb = wm * 32 + mi * 16;
                af[mi][0] = sA[buf][mb + g][c0 + tig];
                af[mi][1] = sA[buf][mb + 8 + g][c0 + tig];
                af[mi][2] = sA[buf][mb + g][c0 + tig + 4];
                af[mi][3] = sA[buf][mb + 8 + g][c0 + tig + 4];
            }
#pragma unroll
            for (int ni = 0; ni < 8; ni++) {
                int nb = wn * 64 + ni * 8;
                uint32_t bf[2];
                bf[0] = sB[buf][nb + g][c0 + tig];
                bf[1] = sB[buf][nb + g][c0 + tig + 4];
                mma16(acc[0][ni], af[0], bf);
                mma16(acc[1][ni], af[1], bf);
            }
        }
        if (ch + 1 < nch) {
            const int nb2 = buf ^ 1;
            *(uint4*)&sA[nb2][mrow][kq] = la0;
            *(uint4*)&sA[nb2][mrow][kq + 4] = la1;
            *(uint4*)&sB[nb2][mrow][kq] = lb0;
            *(uint4*)&sB[nb2][mrow][kq + 4] = lb1;
        }
        __syncthreads();
    }

#pragma unroll
    for (int mi = 0; mi < 2; mi++) {
        int m = m0 + wm * 32 + mi * 16 + g;
#pragma unroll
        for (int ni = 0; ni < 8; ni++) {
            int n = n0 + wn * 64 + ni * 8 + 2 * tig;
            float b0 = bih[n], b1 = bih[n + 1];
            if (n < 2 * H_) { b0 += bhh[n]; b1 += bhh[n + 1]; }
            *(float2*)(g_xg + (size_t)m * G_ + n) =
                make_float2(acc[mi][ni][0] + b0, acc[mi][ni][1] + b1);
            *(float2*)(g_xg + (size_t)(m + 8) * G_ + n) =
                make_float2(acc[mi][ni][2] + b0, acc[mi][ni][3] + b1);
        }
    }
}

// ============================================================================
// Persistent recurrence, 2D ownership: block = (m-group of 32 batch rows) x
// (col-group of 16 hidden cols). 48 W_hh rows resident in smem (fp16).
// Per step: load own 64KB h slice (2 pipelined halves, 2 syncs), mma
// (8 warps = 4 k-quarters x 2 n-halves, k-interleaved slots), 4-way smem
// reduce, gates, grid barrier.
// ============================================================================
__global__ void __launch_bounds__(NTHR, 1) gru_rec(
    const float* __restrict__ Whh, const float* __restrict__ bhh,
    int layer, float* __restrict__ final_out)
{
    extern __shared__ uint32_t smu[];
    uint32_t* ws = smu;                    // [48][WP]
    uint32_t* hs = smu + WS_U;             // [32][HSP]
    float* red = (float*)(smu + WS_U + HS_U);  // [4][32][RPD]

    const int tid = threadIdx.x;
    const int lane = tid & 31, wid = tid >> 5;
    const int g = lane >> 2, tig = lane & 3;
    const int wk = wid & 3;        // k-quarter (slot interleave s%4==wk)
    const int wn = wid >> 2;       // n half (24 rows)
    const int cg = blockIdx.x & 63;
    const int mg = blockIdx.x >> 6;
    const int j0 = cg * 16;        // owned cols [j0, j0+16)
    const int b0 = mg * 32;        // owned batch rows [b0, b0+32)
    const uint32_t hs_b = smem_u32(hs);

    // ---- stage W_hh slice (48 rows x 1024) into smem as fp16 (once) ----
    for (int f = tid; f < 48 * 256; f += NTHR) {
        int v = f >> 8, q = f & 255;            // v: 0..47, q: float4 idx
        int ni = v >> 4, jj = v & 15;
        const float* wr = Whh + (size_t)(ni * H_ + j0 + jj) * H_ + 4 * q;
        float4 w4 = *(const float4*)wr;
        *(uint2*)(ws + (size_t)v * WP + 2 * q) =
            make_uint2(pack2(w4.x, w4.y), pack2(w4.z, w4.w));
    }
    const int bloc = tid >> 3;                  // local batch row 0..31
    const int jj0 = (tid * 2) & 15;             // even col offset 0..14
    const float bhn0 = bhh[2 * H_ + j0 + jj0];
    const float bhn1 = bhh[2 * H_ + j0 + jj0 + 1];
    float hreg[2] = {0.f, 0.f};
    __syncthreads();

    unsigned* barBase = g_barcnt + layer * T_;
    const int srow = tid >> 3;                  // staging row 0..31
    const int sc0 = (tid & 7) * 4;              // staging u32 col base

    for (int t = 0; t < T_; t++) {
        // prefetch gate inputs (hide latency behind mma pipeline)
        const float* xp = g_xg + ((size_t)(b0 + bloc) * T_ + t) * G_ + j0 + jj0;
        float2 xr2 = *(const float2*)xp;
        float2 xz2 = *(const float2*)(xp + H_);
        float2 xn2 = *(const float2*)(xp + 2 * H_);

        float gr[2] = {0.f, 0.f}, gz[2] = {0.f, 0.f}, gn[2] = {0.f, 0.f};

        if (t > 0) {
            const uint32_t* hre = g_hh + (size_t)((t - 1) & 1) * (BH / 2)
                                  + (size_t)b0 * (H_ / 2);

            float acc[2][3][4];
#pragma unroll
            for (int mt = 0; mt < 2; mt++)
#pragma unroll
                for (int ni = 0; ni < 3; ni++)
#pragma unroll
                    for (int q = 0; q < 4; q++) acc[mt][ni][q] = 0.f;

            // issue both halves of the 32x512(u32) h slice
#pragma unroll
            for (int hh = 0; hh < 2; hh++) {
                uint32_t d = hs_b + (uint32_t)(srow * HSP + hh * 256 + sc0) * 4u;
                const uint32_t* s = hre + (size_t)srow * (H_ / 2) + hh * 256 + sc0;
#pragma unroll
                for (int r = 0; r < 8; r++) {
                    asm volatile("cp.async.cg.shared.global [%0], [%1], 16;"
                                 :: "r"(d + r * 128u), "l"(s + r * 32) : "memory");
                }
                asm volatile("cp.async.commit_group;" ::: "memory");
            }

#pragma unroll
            for (int hh = 0; hh < 2; hh++) {
                if (hh == 0) asm volatile("cp.async.wait_group 1;" ::: "memory");
                else         asm volatile("cp.async.wait_group 0;" ::: "memory");
                __syncthreads();

                // 8 k16 slots for this warp in this half: s = hh*32 + wk + 4*u
#pragma unroll
                for (int u = 0; u < 8; u++) {
                    const int s = hh * 32 + wk + 4 * u;
                    const int c0 = s * 8;
                    uint32_t af[2][4];
#pragma unroll
                    for (int mt = 0; mt < 2; mt++) {
                        const uint32_t* r0 = hs + (size_t)(mt * 16 + g) * HSP + c0 + tig;
                        const uint32_t* r1 = hs + (size_t)(mt * 16 + 8 + g) * HSP + c0 + tig;
                        af[mt][0] = r0[0];
                        af[mt][1] = r1[0];
                        af[mt][2] = r0[4];
                        af[mt][3] = r1[4];
                    }
#pragma unroll
                    for (int ni = 0; ni < 3; ni++) {
                        const uint32_t* br = ws + (size_t)(wn * 24 + ni * 8 + g) * WP + c0 + tig;
                        uint32_t bf[2] = {br[0], br[4]};
                        mma16(acc[0][ni], af[0], bf);
                        mma16(acc[1][ni], af[1], bf);
                    }
                }
            }

            // ---- 4-way k reduce via smem: red[wk][m][n] ----
#pragma unroll
            for (int mt = 0; mt < 2; mt++)
#pragma unroll
                for (int ni = 0; ni < 3; ni++) {
                    int n = wn * 24 + ni * 8 + 2 * tig;
                    float* p0 = red + (size_t)(wk * 32 + mt * 16 + g) * RPD + n;
                    *(float2*)p0 = make_float2(acc[mt][ni][0], acc[mt][ni][1]);
                    float* p1 = red + (size_t)(wk * 32 + mt * 16 + 8 + g) * RPD + n;
                    *(float2*)p1 = make_float2(acc[mt][ni][2], acc[mt][ni][3]);
                }
            __syncthreads();

#pragma unroll
            for (int e = 0; e < 2; e++) {
                int jj = jj0 + e;
#pragma unroll
                for (int p = 0; p < 4; p++) {
                    const float* rp = red + (size_t)(p * 32 + bloc) * RPD;
                    gr[e] += rp[jj];
                    gz[e] += rp[16 + jj];
                    gn[e] += rp[32 + jj];
                }
            }
        }

        // ---- gates: 2 adjacent cols per thread ----
        float hn0, hn1;
        {
            float r = 1.f / (1.f + expf(-(xr2.x + gr[0])));
            float z = 1.f / (1.f + expf(-(xz2.x + gz[0])));
            float n = tanhf(xn2.x + r * (gn[0] + bhn0));
            hn0 = (1.f - z) * n + z * hreg[0];
            hreg[0] = hn0;
        }
        {
            float r = 1.f / (1.f + expf(-(xr2.y + gr[1])));
            float z = 1.f / (1.f + expf(-(xz2.y + gz[1])));
            float n = tanhf(xn2.y + r * (gn[1] + bhn1));
            hn1 = (1.f - z) * n + z * hreg[1];
            hreg[1] = hn1;
        }
        const int bG = b0 + bloc;
        const int col = j0 + jj0;
        g_hh[(size_t)(t & 1) * (BH / 2) + (((size_t)bG * H_ + col) >> 1)] = pack2(hn0, hn1);
        if (layer == 0) {
            g_ah[(((size_t)bG * T_ + t) * H_ + col) >> 1] = pack2(hn0, hn1);
        } else if (t == T_ - 1) {
            *(float2*)(final_out + (size_t)bG * H_ + col) = make_float2(hn0, hn1);
        }

        if (t < T_ - 1) grid_bar(barBase + t);
    }
}

// ============================================================================
extern "C" void kernel_launch(void* const* d_in, const int* in_sizes, int n_in,
                              void* d_out, int out_size)
{
    const float* x    = (const float*)d_in[0];
    const float* wih0 = (const float*)d_in[1];
    const float* whh0 = (const float*)d_in[2];
    const float* bih0 = (const float*)d_in[3];
    const float* bhh0 = (const float*)d_in[4];
    const float* wih1 = (const float*)d_in[5];
    const float* whh1 = (const float*)d_in[6];
    const float* bih1 = (const float*)d_in[7];
    const float* bhh1 = (const float*)d_in[8];
    float* out = (float*)d_out;

    cudaFuncSetAttribute(gru_rec, cudaFuncAttributeMaxDynamicSharedMemorySize, REC_SMEM);

    uint32_t* ah;  cudaGetSymbolAddress((void**)&ah, g_ah);
    uint32_t* wh;  cudaGetSymbolAddress((void**)&wh, g_wh);

    dim3 gg(G_ / 128, (B_ * T_) / 128);   // 24 x 256

    reset_barriers<<<1, 2 * T_>>>();

    {
        int n4x = B_ * T_ * I_ / 4;
        cvt16<<<(n4x + 255) / 256, 256>>>(x, ah, n4x);
        int n4w = G_ * I_ / 4;
        cvt16<<<(n4w + 255) / 256, 256>>>(wih0, wh, n4w);
    }
    xg_gemm<<<gg, 256>>>(ah, wh, bih0, bhh0, I_);
    gru_rec<<<NBLK, NTHR, REC_SMEM>>>(whh0, bhh0, 0, out);   // writes g_ah (fp16 hseq)

    {
        int n4w = G_ * H_ / 4;
        cvt16<<<(n4w + 255) / 256, 256>>>(wih1, wh, n4w);
    }
    xg_gemm<<<gg, 256>>>(ah, wh, bih1, bhh1, H_);
    gru_rec<<<NBLK, NTHR, REC_SMEM>>>(whh1, bhh1, 1, out);
}